// round 8
// baseline (speedup 1.0000x reference)
#include <cuda_runtime.h>

#define BB 8
#define TT 2048
#define CC 1024
#define HH 128

#define SCALE 0.04508422f  /* log2(e) / 32 */

// q: packed A-fragments  [qblock(128)][mtile(8)][ksp(8)][lane(32)][8 floats]
// k: packed B-fragments  [batch(8)][ktile(32)][jg(8)][ksp(8)][lane(32)][4 floats]
// v: packed B-fragments  [batch(8)][ktile(32)][jg(8)][dp(8)][lane(32)][4 floats]
__device__ float g_q[BB*TT*HH];
__device__ float g_k[BB*TT*HH];
__device__ float g_v[BB*TT*HH];
// W packed B-fragments [proj(3)][kt(32)][nchunk(16)][ksp(2)][lane(32)][4 floats]
__device__ float g_w[3*CC*HH];

// -------------------------------------------------------------------------
__device__ __forceinline__ float to_tf32(float x) {
    unsigned u;
    asm("cvt.rna.tf32.f32 %0, %1;" : "=r"(u) : "f"(x));
    return __uint_as_float(u);
}
__device__ __forceinline__ unsigned cvt_u(unsigned x) {
    unsigned u;
    asm("cvt.rna.tf32.f32 %0, %1;" : "=r"(u) : "f"(__uint_as_float(x)));
    return u;
}
__device__ __forceinline__ float ex2(float x) {
    float y;
    asm("ex2.approx.f32 %0, %1;" : "=f"(y) : "f"(x));
    return y;
}
__device__ __forceinline__ void mma8(float* c, const unsigned* A, const unsigned* B) {
    asm volatile(
        "mma.sync.aligned.m16n8k8.row.col.f32.tf32.tf32.f32 "
        "{%0,%1,%2,%3}, {%4,%5,%6,%7}, {%8,%9}, {%0,%1,%2,%3};\n"
        : "+f"(c[0]), "+f"(c[1]), "+f"(c[2]), "+f"(c[3])
        : "r"(A[0]), "r"(A[1]), "r"(A[2]), "r"(A[3]), "r"(B[0]), "r"(B[1]));
}
__device__ __forceinline__ void cp16(unsigned dst, const void* src) {
    asm volatile("cp.async.cg.shared.global [%0], [%1], 16;" :: "r"(dst), "l"(src));
}
__device__ __forceinline__ void cp_commit() { asm volatile("cp.async.commit_group;"); }
__device__ __forceinline__ void cp_wait1()  { asm volatile("cp.async.wait_group 1;"); }

// -------------------------------------------------------------------------
// Prepass: round W to tf32 and pack into B-fragment layout.
// -------------------------------------------------------------------------
__global__ void pack_w(const float* __restrict__ W0, const float* __restrict__ W1,
                       const float* __restrict__ W2) {
    int f = blockIdx.x * 256 + threadIdx.x;
    int lane = f & 31;
    int ksp  = (f >> 5) & 1;
    int nchunk = (f >> 6) & 15;
    int kt = (f >> 10) & 31;
    int y  = f >> 15;
    const float* W = (y == 0) ? W0 : (y == 1) ? W1 : W2;
    int g = lane >> 2, t = lane & 3;
    int ke = kt * 32 + ksp * 16;
    int col = nchunk * 8 + g;
    float4 o;
    o.x = to_tf32(W[(size_t)(ke + t)     * HH + col]);
    o.y = to_tf32(W[(size_t)(ke + t + 4) * HH + col]);
    o.z = to_tf32(W[(size_t)(ke + 8 + t)     * HH + col]);
    o.w = to_tf32(W[(size_t)(ke + 8 + t + 4) * HH + col]);
    *(float4*)(g_w + (size_t)f * 4) = o;
}

// -------------------------------------------------------------------------
// Kernel 1: QKV projection (round-6 verbatim, known good).
// -------------------------------------------------------------------------
#define XP 36
#define XBUF (128 * XP)
#define WTILE 4096
#define QKV_SMEM ((2 * XBUF + 2 * WTILE) * 4)   // 69632 B

__global__ __launch_bounds__(256, 2) void qkv_mma(const float* __restrict__ x) {
    extern __shared__ float sm[];
    float* xs = sm;
    float* ws = sm + 2 * XBUF;
    unsigned sm_base = (unsigned)__cvta_generic_to_shared(sm);

    const int tid  = threadIdx.x;
    const int warp = tid >> 5;
    const int lane = tid & 31;
    const int g = lane >> 2;
    const int t = lane & 3;
    const int wm = warp >> 1;
    const int wn = warp & 1;
    const int proj = blockIdx.x;    // 0=q 1=k 2=v
    const int rb   = blockIdx.y;

    const float* xb = x + (size_t)rb * 128 * CC;
    const float* wb = g_w + (size_t)proj * 32 * WTILE;

    auto issue_x = [&](int buf, int k0) {
#pragma unroll
        for (int i = 0; i < 4; i++) {
            int f = tid + i * 256;
            int row = f >> 3, c4 = f & 7;
            cp16(sm_base + (buf * XBUF + row * XP + c4 * 4) * 4,
                 xb + (size_t)row * CC + k0 + c4 * 4);
        }
    };
    auto issue_w = [&](int buf, int kt) {
#pragma unroll
        for (int i = 0; i < 4; i++) {
            int f = tid + i * 256;
            cp16(sm_base + (2 * XBUF + buf * WTILE + f * 4) * 4,
                 wb + (size_t)kt * WTILE + f * 4);
        }
    };

    float o[2][8][4];
#pragma unroll
    for (int mt = 0; mt < 2; mt++)
#pragma unroll
        for (int nt = 0; nt < 8; nt++)
#pragma unroll
            for (int e = 0; e < 4; e++) o[mt][nt][e] = 0.0f;

    issue_x(0, 0);
    issue_w(0, 0);
    cp_commit();

    for (int kt = 0; kt < 32; kt++) {
        __syncthreads();
        if (kt + 1 < 32) { issue_x((kt + 1) & 1, (kt + 1) * 32); issue_w((kt + 1) & 1, kt + 1); }
        cp_commit();
        cp_wait1();
        __syncthreads();

        const unsigned* xu = (const unsigned*)(xs + (kt & 1) * XBUF);
        const float4*   w4 = (const float4*)(ws + (kt & 1) * WTILE);

#pragma unroll
        for (int ksp = 0; ksp < 2; ksp++) {
            unsigned aE[2][4], aO[2][4];
#pragma unroll
            for (int mt = 0; mt < 2; mt++) {
                int r = wm * 32 + mt * 16;
                int cb = ksp * 16;
                aE[mt][0] = cvt_u(xu[(r + g)     * XP + cb + t]);
                aE[mt][1] = cvt_u(xu[(r + g + 8) * XP + cb + t]);
                aE[mt][2] = cvt_u(xu[(r + g)     * XP + cb + t + 4]);
                aE[mt][3] = cvt_u(xu[(r + g + 8) * XP + cb + t + 4]);
                aO[mt][0] = cvt_u(xu[(r + g)     * XP + cb + 8 + t]);
                aO[mt][1] = cvt_u(xu[(r + g + 8) * XP + cb + 8 + t]);
                aO[mt][2] = cvt_u(xu[(r + g)     * XP + cb + 8 + t + 4]);
                aO[mt][3] = cvt_u(xu[(r + g + 8) * XP + cb + 8 + t + 4]);
            }
#pragma unroll
            for (int nt = 0; nt < 8; nt++) {
                int nchunk = wn * 8 + nt;
                float4 bb = w4[(nchunk * 2 + ksp) * 32 + lane];
                mma8(o[0][nt], aE[0], (const unsigned*)&bb.x);
                mma8(o[0][nt], aO[0], (const unsigned*)&bb.z);
                mma8(o[1][nt], aE[1], (const unsigned*)&bb.x);
                mma8(o[1][nt], aO[1], (const unsigned*)&bb.z);
            }
        }
    }

    // ---- epilogue: C-frags -> packed fragment layouts (shuffles hoisted) ----
    const int srcA = (lane & ~3) | (t >> 1);
    const int srcB = srcA + 2;
    const bool selA = (t & 1);
    const int srcV0 = (lane & 3) * 4 + (lane >> 3);
    const int srcV1 = srcV0 + 16;
    const bool selV = ((lane >> 2) & 1);

#pragma unroll
    for (int mt = 0; mt < 2; mt++) {
#pragma unroll
        for (int nt = 0; nt < 8; nt++) {
            float r0, r1, r2, r3;
            if (proj == 0) { r0 = o[mt][nt][0]; r1 = o[mt][nt][1]; r2 = o[mt][nt][2]; r3 = o[mt][nt][3]; }
            else { r0 = to_tf32(o[mt][nt][0]); r1 = to_tf32(o[mt][nt][1]);
                   r2 = to_tf32(o[mt][nt][2]); r3 = to_tf32(o[mt][nt][3]); }
            int dchunk = wn * 8 + nt;

            if (proj == 0) {
                float c0a = __shfl_sync(~0u, r0, srcA), c1a = __shfl_sync(~0u, r1, srcA);
                float c2a = __shfl_sync(~0u, r2, srcA), c3a = __shfl_sync(~0u, r3, srcA);
                float c0b = __shfl_sync(~0u, r0, srcB), c1b = __shfl_sync(~0u, r1, srcB);
                float c2b = __shfl_sync(~0u, r2, srcB), c3b = __shfl_sync(~0u, r3, srcB);
                float4 a;
                a.x = to_tf32((selA ? c1a : c0a) * SCALE);
                a.y = to_tf32((selA ? c3a : c2a) * SCALE);
                a.z = to_tf32((selA ? c1b : c0b) * SCALE);
                a.w = to_tf32((selA ? c3b : c2b) * SCALE);
                int mtile = wm * 2 + mt;
                int ksp = dchunk >> 1, half = dchunk & 1;
                float4* dst = (float4*)g_q + (size_t)rb * 4096 +
                              ((mtile * 8 + ksp) * 32 + lane) * 2 + half;
                *dst = a;
            } else if (proj == 1) {
                float c0a = __shfl_sync(~0u, r0, srcA), c1a = __shfl_sync(~0u, r1, srcA);
                float c2a = __shfl_sync(~0u, r2, srcA), c3a = __shfl_sync(~0u, r3, srcA);
                float c0b = __shfl_sync(~0u, r0, srcB), c1b = __shfl_sync(~0u, r1, srcB);
                float c2b = __shfl_sync(~0u, r2, srcB), c3b = __shfl_sync(~0u, r3, srcB);
                float b00 = selA ? c1a : c0a;
                float b01 = selA ? c1b : c0b;
                float b10 = selA ? c3a : c2a;
                float b11 = selA ? c3b : c2b;
                int key0 = wm * 32 + mt * 16;
                int batch = rb >> 4;
                int ktile = (rb & 15) * 2 + (key0 >> 6);
                int jg0 = (key0 & 63) >> 3;
                int ksp = dchunk >> 1, half = dchunk & 1;
                float2* base = (float2*)g_k + (size_t)(batch * 32 + ktile) * 4096;
                base[((jg0 * 8 + ksp) * 32 + lane) * 2 + half]       = make_float2(b00, b01);
                base[(((jg0 + 1) * 8 + ksp) * 32 + lane) * 2 + half] = make_float2(b10, b11);
            } else {
                float d0a = __shfl_sync(~0u, r0, srcV0), d1a = __shfl_sync(~0u, r1, srcV0);
                float d2a = __shfl_sync(~0u, r2, srcV0), d3a = __shfl_sync(~0u, r3, srcV0);
                float d0b = __shfl_sync(~0u, r0, srcV1), d1b = __shfl_sync(~0u, r1, srcV1);
                float d2b = __shfl_sync(~0u, r2, srcV1), d3b = __shfl_sync(~0u, r3, srcV1);
                float b00 = selV ? d1a : d0a;
                float b01 = selV ? d1b : d0b;
                float b10 = selV ? d3a : d2a;
                float b11 = selV ? d3b : d2b;
                int key0 = wm * 32 + mt * 16;
                int batch = rb >> 4;
                int ktile = (rb & 15) * 2 + (key0 >> 6);
                int jg0 = (key0 & 63) >> 3;
                int dp = dchunk >> 1, half = dchunk & 1;
                float2* base = (float2*)g_v + (size_t)(batch * 32 + ktile) * 4096;
                base[((jg0 * 8 + dp) * 32 + lane) * 2 + half]       = make_float2(b00, b01);
                base[(((jg0 + 1) * 8 + dp) * 32 + lane) * 2 + half] = make_float2(b10, b11);
            }
        }
    }
}

// -------------------------------------------------------------------------
// Kernel 2: flash attention, paired K-tiles (128-key softmax period).
// grid=128, block=256 (8 warps x 16 q-rows).
// smem: Q 64KB + K pair 64KB + V pair 64KB = 192KB (alternating reload).
// Pipeline: V(p) loads overlap S(p); K(p+1) loads overlap softmax+PV(p).
// -------------------------------------------------------------------------
#define Q_F 16384
#define KV_F 8192
#define K_OFF Q_F
#define V_OFF (Q_F + 2 * KV_F)
#define ATTN_SMEM ((Q_F + 4 * KV_F) * 4)   // 196608 B

__global__ __launch_bounds__(256, 1) void attn_mma(float* __restrict__ out) {
    extern __shared__ float sm[];
    unsigned sm_base = (unsigned)__cvta_generic_to_shared(sm);

    const int tid  = threadIdx.x;
    const int warp = tid >> 5;
    const int lane = tid & 31;
    const int g = lane >> 2;
    const int t = lane & 3;

    const int qrow0 = blockIdx.x * 128;
    const int batch = blockIdx.x >> 4;
    const float* kb = g_k + (size_t)batch * 32 * KV_F;
    const float* vb = g_v + (size_t)batch * 32 * KV_F;
    const float* qb = g_q + (size_t)blockIdx.x * Q_F;

    // pair loads: tiles 2p, 2p+1 are contiguous (16384 floats)
    auto issue_kpair = [&](int p) {
        const float* src = kb + (size_t)p * 2 * KV_F;
#pragma unroll
        for (int i = 0; i < 16; i++) {
            int f = tid + i * 256;
            cp16(sm_base + (K_OFF + f * 4) * 4, src + (size_t)f * 4);
        }
    };
    auto issue_vpair = [&](int p) {
        const float* src = vb + (size_t)p * 2 * KV_F;
#pragma unroll
        for (int i = 0; i < 16; i++) {
            int f = tid + i * 256;
            cp16(sm_base + (V_OFF + f * 4) * 4, src + (size_t)f * 4);
        }
    };

    // group 1: Q + K pair 0;  group 2: V pair 0
#pragma unroll
    for (int i = 0; i < 16; i++) {
        int f = tid + i * 256;
        cp16(sm_base + f * 16, qb + (size_t)f * 4);
    }
    issue_kpair(0);
    cp_commit();
    issue_vpair(0);
    cp_commit();

    float o[16][4];
    float m[2] = {-1e30f, -1e30f}, l[2] = {0.0f, 0.0f};
#pragma unroll
    for (int nt = 0; nt < 16; nt++)
#pragma unroll
        for (int e = 0; e < 4; e++) o[nt][e] = 0.0f;

    const float4* Q4 = (const float4*)sm;
    const int srcA = (lane & ~3) | (t >> 1);
    const int srcB = srcA + 2;
    const bool odd = (t & 1);

    for (int p = 0; p < 16; p++) {
        cp_wait1();          // Q+K pair p resident (V pair may still be in flight)
        __syncthreads();

        // ---- S = Q @ K^T over 128 keys (two 64-key halves) ----
        float s[16][4];
#pragma unroll
        for (int j = 0; j < 16; j++)
#pragma unroll
            for (int e = 0; e < 4; e++) s[j][e] = 0.0f;

#pragma unroll
        for (int h = 0; h < 2; h++) {
            const float4* K4 = (const float4*)(sm + K_OFF + h * KV_F);
#pragma unroll
            for (int ksp = 0; ksp < 8; ksp++) {
                float4 aE = Q4[((warp * 8 + ksp) * 32 + lane) * 2 + 0];
                float4 aO = Q4[((warp * 8 + ksp) * 32 + lane) * 2 + 1];
#pragma unroll
                for (int jg = 0; jg < 8; jg++) {
                    float4 bb = K4[(jg * 8 + ksp) * 32 + lane];
                    mma8(s[h * 8 + jg], (const unsigned*)&aE, (const unsigned*)&bb.x);
                    mma8(s[h * 8 + jg], (const unsigned*)&aO, (const unsigned*)&bb.z);
                }
            }
        }
        __syncthreads();     // all warps done reading K bufs

        // prefetch next K pair (overlaps softmax + PV)
        if (p + 1 < 16) issue_kpair(p + 1);
        cp_commit();

        // ---- softmax over 128 keys (regs only) ----
        {
            float mx0 = -1e30f, mx1 = -1e30f;
#pragma unroll
            for (int j = 0; j < 16; j++) {
                mx0 = fmaxf(mx0, fmaxf(s[j][0], s[j][1]));
                mx1 = fmaxf(mx1, fmaxf(s[j][2], s[j][3]));
            }
#pragma unroll
            for (int off = 1; off <= 2; off <<= 1) {
                mx0 = fmaxf(mx0, __shfl_xor_sync(~0u, mx0, off));
                mx1 = fmaxf(mx1, __shfl_xor_sync(~0u, mx1, off));
            }
            bool need = (mx0 > m[0]) || (mx1 > m[1]);   // exact: c==1 when false
            float mn0 = fmaxf(m[0], mx0), mn1 = fmaxf(m[1], mx1);
            float c0 = ex2(m[0] - mn0), c1 = ex2(m[1] - mn1);
            m[0] = mn0; m[1] = mn1;
            float s0 = 0.0f, s1 = 0.0f;
#pragma unroll
            for (int j = 0; j < 16; j++) {
                float p0 = ex2(s[j][0] - mn0);
                float p1 = ex2(s[j][1] - mn0);
                float p2 = ex2(s[j][2] - mn1);
                float p3 = ex2(s[j][3] - mn1);
                s0 += p0 + p1; s1 += p2 + p3;
                s[j][0] = to_tf32(p0); s[j][1] = to_tf32(p1);
                s[j][2] = to_tf32(p2); s[j][3] = to_tf32(p3);
            }
#pragma unroll
            for (int off = 1; off <= 2; off <<= 1) {
                s0 += __shfl_xor_sync(~0u, s0, off);
                s1 += __shfl_xor_sync(~0u, s1, off);
            }
            l[0] = l[0] * c0 + s0;
            l[1] = l[1] * c1 + s1;
            if (need) {
#pragma unroll
                for (int nt = 0; nt < 16; nt++) {
                    o[nt][0] *= c0; o[nt][1] *= c0;
                    o[nt][2] *= c1; o[nt][3] *= c1;
                }
            }
        }

        cp_wait1();          // V pair p resident (K pair p+1 in flight)
        __syncthreads();

        // ---- O += P @ V over both halves ----
#pragma unroll
        for (int h = 0; h < 2; h++) {
            const float4* V4 = (const float4*)(sm + V_OFF + h * KV_F);
#pragma unroll
            for (int jg = 0; jg < 8; jg++) {
                unsigned pa[4];
                {
                    float* sj = s[h * 8 + jg];
                    float u0 = __shfl_sync(~0u, sj[0], srcA);
                    float u1 = __shfl_sync(~0u, sj[1], srcA);
                    float w0 = __shfl_sync(~0u, sj[0], srcB);
                    float w1 = __shfl_sync(~0u, sj[1], srcB);
                    float v0 = __shfl_sync(~0u, sj[2], srcA);
                    float v1 = __shfl_sync(~0u, sj[3], srcA);
                    float x0 = __shfl_sync(~0u, sj[2], srcB);
                    float x1 = __shfl_sync(~0u, sj[3], srcB);
                    pa[0] = __float_as_uint(odd ? u1 : u0);
                    pa[1] = __float_as_uint(odd ? v1 : v0);
                    pa[2] = __float_as_uint(odd ? w1 : w0);
                    pa[3] = __float_as_uint(odd ? x1 : x0);
                }
#pragma unroll
                for (int dp = 0; dp < 8; dp++) {
                    float4 bb = V4[(jg * 8 + dp) * 32 + lane];
                    mma8(o[2 * dp],     pa, (const unsigned*)&bb.x);
                    mma8(o[2 * dp + 1], pa, (const unsigned*)&bb.z);
                }
            }
        }
        __syncthreads();     // all warps done reading V bufs

        // prefetch next V pair (overlaps next S phase)
        if (p + 1 < 16) issue_vpair(p + 1);
        cp_commit();
    }

    // ---- epilogue ----
    {
        float inv0 = 1.0f / l[0];
        float inv1 = 1.0f / l[1];
        size_t r0 = (size_t)qrow0 + warp * 16 + g;
#pragma unroll
        for (int nt = 0; nt < 16; nt++) {
            int c = nt * 8 + 2 * t;
            *(float2*)(out + r0 * HH + c) =
                make_float2(o[nt][0] * inv0, o[nt][1] * inv0);
            *(float2*)(out + (r0 + 8) * HH + c) =
                make_float2(o[nt][2] * inv1, o[nt][3] * inv1);
        }
    }
}

// -------------------------------------------------------------------------
extern "C" void kernel_launch(void* const* d_in, const int* in_sizes, int n_in,
                              void* d_out, int out_size) {
    const float* x  = (const float*)d_in[0];
    const float* Wk = (const float*)d_in[1];
    const float* Wq = (const float*)d_in[2];
    const float* Wv = (const float*)d_in[3];
    float* out = (float*)d_out;

    pack_w<<<384, 256>>>(Wq, Wk, Wv);

    cudaFuncSetAttribute(qkv_mma, cudaFuncAttributeMaxDynamicSharedMemorySize, QKV_SMEM);
    qkv_mma<<<dim3(3, 128), 256, QKV_SMEM>>>(x);

    cudaFuncSetAttribute(attn_mma, cudaFuncAttributeMaxDynamicSharedMemorySize, ATTN_SMEM);
    attn_mma<<<128, 256, ATTN_SMEM>>>(out);
}